// round 1
// baseline (speedup 1.0000x reference)
#include <cuda_runtime.h>
#include <cuda_bf16.h>
#include <math.h>

#define NB 1024   // batches
#define NN 64     // nodes
#define DD 128    // feature dim
#define EE 1024   // edges
#define HH 4      // heads
#define CC 32     // per-head dim
#define KK 5
#define LL 2

// CSR of edges grouped by dst, deterministic (edge order preserved)
__device__ int g_off[NN + 1];
__device__ int g_csr[EE];

__global__ void build_csr_kernel(const int* __restrict__ ei) {
    const int n = threadIdx.x;           // 64 threads
    const int* dst = ei + EE;
    __shared__ int deg[NN];
    int cnt = 0;
    for (int e = 0; e < EE; ++e) cnt += (dst[e] == n);
    deg[n] = cnt;
    __syncthreads();
    if (n == 0) {
        int s = 0;
        for (int i = 0; i < NN; ++i) { g_off[i] = s; s += deg[i]; }
        g_off[NN] = s;
    }
    __syncthreads();
    int p = g_off[n];
    for (int e = 0; e < EE; ++e) {
        if (dst[e] == n) g_csr[p++] = e;
    }
}

// 64x128 = (64x128 smem) @ (128x128 gmem) + bias, result to smem
__device__ __forceinline__ void gemm_64x128(const float* __restrict__ A,
                                            const float* __restrict__ W,
                                            const float* __restrict__ bias,
                                            float* __restrict__ dstS, int tid) {
    const int j = tid & 127;
    const int half = tid >> 7;
    const float* a0 = A + (half * 32) * DD;
    float acc[32];
    const float bv = bias[j];
#pragma unroll
    for (int r = 0; r < 32; ++r) acc[r] = bv;
    for (int k = 0; k < DD; k += 4) {
        const float w0 = W[(k + 0) * DD + j];
        const float w1 = W[(k + 1) * DD + j];
        const float w2 = W[(k + 2) * DD + j];
        const float w3 = W[(k + 3) * DD + j];
#pragma unroll
        for (int r = 0; r < 32; ++r) {
            const float4 hv = *(const float4*)(a0 + r * DD + k);
            acc[r] = fmaf(hv.x, w0, acc[r]);
            acc[r] = fmaf(hv.y, w1, acc[r]);
            acc[r] = fmaf(hv.z, w2, acc[r]);
            acc[r] = fmaf(hv.w, w3, acc[r]);
        }
    }
#pragma unroll
    for (int r = 0; r < 32; ++r) dstS[(half * 32 + r) * DD + j] = acc[r];
}

__global__ __launch_bounds__(256, 1) void gat_kernel(
    const int* __restrict__ x, const int* __restrict__ ei, const float* __restrict__ ea,
    const float* __restrict__ attr_emb, const float* __restrict__ opt_emb,
    const float* __restrict__ prior,
    const float* __restrict__ Wl, const float* __restrict__ bl,
    const float* __restrict__ Wr, const float* __restrict__ br,
    const float* __restrict__ We, const float* __restrict__ att,
    const float* __restrict__ conv_bias, const float* __restrict__ ln_g,
    const float* __restrict__ ln_b,
    const float* __restrict__ W1, const float* __restrict__ b1,
    const float* __restrict__ W2, const float* __restrict__ b2,
    float* __restrict__ out) {
    extern __shared__ float sm[];
    float* h_s     = sm;                       // 8192
    float* t0_s    = h_s + NN * DD;            // 8192
    float* xl_s    = t0_s + NN * DD;           // 8192
    float* xr_s    = xl_s + NN * DD;           // 8192 (reused as out accumulator)
    float* alpha_s = xr_s + NN * DD;           // 4096
    float* ea_s    = alpha_s + EE * HH;        // 1024
    int*   src_s   = (int*)(ea_s + EE);        // 1024
    int*   dst_s   = src_s + EE;               // 1024
    float* rel_s   = (float*)(dst_s + EE);     // 64

    const int b = blockIdx.x;
    const int tid = threadIdx.x;
    const int lane = tid & 31;
    const int w = tid >> 5;

    // ---- load edge data ----
    for (int e = tid; e < EE; e += 256) {
        ea_s[e] = ea[e];
        src_s[e] = ei[e];
        dst_s[e] = ei[EE + e];
    }
    // ---- T0 = (attr_emb + opt_emb[n, x]) * prior ----
    for (int idx = tid; idx < NN * DD; idx += 256) {
        const int n = idx >> 7, d = idx & 127;
        const int xv = x[b * NN + n];
        const float v = (attr_emb[idx] + opt_emb[(n * KK + xv) * DD + d]) * prior[n];
        t0_s[idx] = v;
        h_s[idx] = v;
    }
    __syncthreads();

    for (int l = 0; l < LL; ++l) {
        // ---- xl = h@Wl + bl ; xr = h@Wr + br ----
        gemm_64x128(h_s, Wl + l * DD * DD, bl + l * DD, xl_s, tid);
        gemm_64x128(h_s, Wr + l * DD * DD, br + l * DD, xr_s, tid);
        __syncthreads();

        // ---- alpha[e,h] = sum_c leaky(xl[src]+xr[dst]+ea*We) * att ----
        {
            const int head = w & 3;
            const int half = w >> 2;
            const int d = head * CC + lane;
            const float we_v = We[l * DD + d];
            const float att_v = att[l * DD + d];   // (L,H,C) contiguous == l*128+d
            for (int e = half; e < EE; e += 2) {
                const int s = src_s[e];
                const int t = dst_s[e];
                float z = xl_s[s * DD + d] + xr_s[t * DD + d] + ea_s[e] * we_v;
                z = z > 0.f ? z : 0.2f * z;
                float p = z * att_v;
#pragma unroll
                for (int o = 16; o; o >>= 1) p += __shfl_xor_sync(0xffffffffu, p, o);
                if (lane == 0) alpha_s[e * HH + head] = p;
            }
        }
        __syncthreads();

        // ---- softmax over incoming edges per (node, head) ----
        {
            const int n = tid >> 2, head = tid & 3;   // 256 threads == 64*4
            const int e0 = g_off[n], e1 = g_off[n + 1];
            if (e1 > e0) {
                float m = -INFINITY;
                for (int i = e0; i < e1; ++i)
                    m = fmaxf(m, alpha_s[g_csr[i] * HH + head]);
                float den = 0.f;
                for (int i = e0; i < e1; ++i) {
                    const int e = g_csr[i];
                    const float ex = expf(alpha_s[e * HH + head] - m);
                    alpha_s[e * HH + head] = ex;
                    den += ex;
                }
                const float inv = 1.f / den;
                for (int i = e0; i < e1; ++i) alpha_s[g_csr[i] * HH + head] *= inv;
            }
        }
        __syncthreads();

        // ---- aggregate: out[n,d] = sum_{e in in(n)} xl[src[e],d] * a[e,h]   (into xr_s) ----
        {
            const int d = tid & 127;
            const int half = tid >> 7;
            const int head = d >> 5;
            for (int nn = half; nn < NN; nn += 2) {
                float acc = 0.f;
                const int e0 = g_off[nn], e1 = g_off[nn + 1];
                for (int i = e0; i < e1; ++i) {
                    const int e = g_csr[i];
                    acc = fmaf(xl_s[src_s[e] * DD + d], alpha_s[e * HH + head], acc);
                }
                xr_s[nn * DD + d] = acc;
            }
        }
        __syncthreads();

        // ---- g = LN(out + conv_bias); h += elu(g)   (warp per node) ----
        {
            for (int n = w; n < NN; n += 8) {
                float4 gv = *(const float4*)(xr_s + n * DD + lane * 4);
                float v[4];
                v[0] = gv.x + conv_bias[l * DD + lane * 4 + 0];
                v[1] = gv.y + conv_bias[l * DD + lane * 4 + 1];
                v[2] = gv.z + conv_bias[l * DD + lane * 4 + 2];
                v[3] = gv.w + conv_bias[l * DD + lane * 4 + 3];
                float sum = v[0] + v[1] + v[2] + v[3];
                float sq = v[0] * v[0] + v[1] * v[1] + v[2] * v[2] + v[3] * v[3];
#pragma unroll
                for (int o = 16; o; o >>= 1) {
                    sum += __shfl_xor_sync(0xffffffffu, sum, o);
                    sq  += __shfl_xor_sync(0xffffffffu, sq, o);
                }
                const float mu = sum * (1.f / DD);
                const float var = sq * (1.f / DD) - mu * mu;
                const float rstd = rsqrtf(var + 1e-5f);
#pragma unroll
                for (int i = 0; i < 4; ++i) {
                    const int d = lane * 4 + i;
                    float t = (v[i] - mu) * rstd * ln_g[l * DD + d] + ln_b[l * DD + d];
                    t = t > 0.f ? t : expm1f(t);
                    h_s[n * DD + d] += t;
                }
            }
        }
        __syncthreads();
    }

    // ---- MLP: q = relu([T0, h] @ W1 + b1)  -> xl_s ----
    {
        const int j = tid & 127;
        const int half = tid >> 7;
        float acc[32];
        const float bv = b1[j];
#pragma unroll
        for (int r = 0; r < 32; ++r) acc[r] = bv;
        const float* a0 = t0_s + (half * 32) * DD;
        for (int k = 0; k < DD; k += 4) {
            const float w0 = W1[(k + 0) * DD + j];
            const float w1 = W1[(k + 1) * DD + j];
            const float w2 = W1[(k + 2) * DD + j];
            const float w3 = W1[(k + 3) * DD + j];
#pragma unroll
            for (int r = 0; r < 32; ++r) {
                const float4 hv = *(const float4*)(a0 + r * DD + k);
                acc[r] = fmaf(hv.x, w0, acc[r]);
                acc[r] = fmaf(hv.y, w1, acc[r]);
                acc[r] = fmaf(hv.z, w2, acc[r]);
                acc[r] = fmaf(hv.w, w3, acc[r]);
            }
        }
        const float* a1 = h_s + (half * 32) * DD;
        for (int k = 0; k < DD; k += 4) {
            const float w0 = W1[(DD + k + 0) * DD + j];
            const float w1 = W1[(DD + k + 1) * DD + j];
            const float w2 = W1[(DD + k + 2) * DD + j];
            const float w3 = W1[(DD + k + 3) * DD + j];
#pragma unroll
            for (int r = 0; r < 32; ++r) {
                const float4 hv = *(const float4*)(a1 + r * DD + k);
                acc[r] = fmaf(hv.x, w0, acc[r]);
                acc[r] = fmaf(hv.y, w1, acc[r]);
                acc[r] = fmaf(hv.z, w2, acc[r]);
                acc[r] = fmaf(hv.w, w3, acc[r]);
            }
        }
#pragma unroll
        for (int r = 0; r < 32; ++r)
            xl_s[(half * 32 + r) * DD + j] = fmaxf(acc[r], 0.f);
    }
    __syncthreads();

    // ---- rel[n] = sigmoid(q[n] . W2 + b2)   (warp per node) ----
    {
        const long long OR = (long long)NB * DD;
        for (int n = w; n < NN; n += 8) {
            float p = 0.f;
            for (int jj = lane; jj < DD; jj += 32)
                p = fmaf(xl_s[n * DD + jj], W2[jj], p);
#pragma unroll
            for (int o = 16; o; o >>= 1) p += __shfl_xor_sync(0xffffffffu, p, o);
            if (lane == 0) {
                const float r = 1.f / (1.f + expf(-(p + b2[0])));
                rel_s[n] = r;
                out[OR + (long long)b * NN + n] = r;
            }
        }
    }
    __syncthreads();

    // ---- hat_T output: [T0, h] ----
    {
        const long long OH = (long long)NB * DD + (long long)NB * NN;
        for (int idx = tid; idx < NN * DD; idx += 256) {
            const int n = idx >> 7, d = idx & 127;
            const long long base = OH + ((long long)b * NN + n) * (2 * DD);
            out[base + d] = t0_s[idx];
            out[base + DD + d] = h_s[idx];
        }
    }

    // ---- f_scale[b,d] = sum_n h*rel / (sum_n rel + 1e-8) ----
    if (tid < DD) {
        float s = 0.f, num = 0.f;
        for (int n = 0; n < NN; ++n) {
            s += rel_s[n];
            num = fmaf(h_s[n * DD + tid], rel_s[n], num);
        }
        out[(long long)b * DD + tid] = num / (s + 1e-8f);
    }
}

extern "C" void kernel_launch(void* const* d_in, const int* in_sizes, int n_in,
                              void* d_out, int out_size) {
    const int*   x         = (const int*)d_in[0];
    const int*   ei        = (const int*)d_in[1];
    const float* ea        = (const float*)d_in[2];
    const float* attr_emb  = (const float*)d_in[3];
    const float* opt_emb   = (const float*)d_in[4];
    const float* prior     = (const float*)d_in[5];
    const float* Wl        = (const float*)d_in[6];
    const float* bl        = (const float*)d_in[7];
    const float* Wr        = (const float*)d_in[8];
    const float* br        = (const float*)d_in[9];
    const float* We        = (const float*)d_in[10];
    const float* att       = (const float*)d_in[11];
    const float* conv_bias = (const float*)d_in[12];
    const float* ln_g      = (const float*)d_in[13];
    const float* ln_b      = (const float*)d_in[14];
    const float* W1        = (const float*)d_in[15];
    const float* b1        = (const float*)d_in[16];
    const float* W2        = (const float*)d_in[17];
    const float* b2        = (const float*)d_in[18];
    float* out = (float*)d_out;

    const size_t smem = (4 * NN * DD + EE * HH + EE) * sizeof(float)
                        + 2 * EE * sizeof(int) + NN * sizeof(float);
    cudaFuncSetAttribute(gat_kernel, cudaFuncAttributeMaxDynamicSharedMemorySize, (int)smem);

    build_csr_kernel<<<1, 64>>>(ei);
    gat_kernel<<<NB, 256, smem>>>(x, ei, ea, attr_emb, opt_emb, prior,
                                  Wl, bl, Wr, br, We, att, conv_bias,
                                  ln_g, ln_b, W1, b1, W2, b2, out);
}

// round 2
// speedup vs baseline: 1.9974x; 1.9974x over previous
#include <cuda_runtime.h>
#include <cuda_bf16.h>
#include <math.h>

#define NB 1024   // batches
#define NN 64     // nodes
#define DD 128    // feature dim
#define EE 1024   // edges
#define HH 4      // heads
#define CC 32     // per-head dim
#define KK 5
#define LL 2

// Edge data sorted by dst (CSR order), built once per launch
__device__ int   g_off[NN + 1];
__device__ int   g_srcp[EE];
__device__ float g_eap[EE];

__global__ void build_csr_kernel(const int* __restrict__ ei, const float* __restrict__ ea) {
    const int n = threadIdx.x;           // 64 threads
    const int* src = ei;
    const int* dst = ei + EE;
    __shared__ int deg[NN];
    int cnt = 0;
    for (int e = 0; e < EE; ++e) cnt += (dst[e] == n);
    deg[n] = cnt;
    __syncthreads();
    if (n == 0) {
        int s = 0;
        for (int i = 0; i < NN; ++i) { g_off[i] = s; s += deg[i]; }
        g_off[NN] = s;
    }
    __syncthreads();
    int p = g_off[n];
    for (int e = 0; e < EE; ++e) {
        if (dst[e] == n) { g_srcp[p] = src[e]; g_eap[p] = ea[e]; ++p; }
    }
}

// 64x128 = (64x128 smem A) @ (128x128 gmem W) + bias -> smem, 512 threads
__device__ __forceinline__ void gemm512(const float* __restrict__ A,
                                        const float* __restrict__ W,
                                        const float* __restrict__ bias,
                                        float* __restrict__ dstS, int tid) {
    const int j = tid & 127;
    const int q = tid >> 7;              // 0..3, 16 rows each
    const float* a0 = A + (q * 16) * DD;
    float acc[16];
    const float bv = bias[j];
#pragma unroll
    for (int r = 0; r < 16; ++r) acc[r] = bv;
    for (int k = 0; k < DD; k += 4) {
        const float w0 = W[(k + 0) * DD + j];
        const float w1 = W[(k + 1) * DD + j];
        const float w2 = W[(k + 2) * DD + j];
        const float w3 = W[(k + 3) * DD + j];
#pragma unroll
        for (int r = 0; r < 16; ++r) {
            const float4 hv = *(const float4*)(a0 + r * DD + k);
            acc[r] = fmaf(hv.x, w0, acc[r]);
            acc[r] = fmaf(hv.y, w1, acc[r]);
            acc[r] = fmaf(hv.z, w2, acc[r]);
            acc[r] = fmaf(hv.w, w3, acc[r]);
        }
    }
#pragma unroll
    for (int r = 0; r < 16; ++r) dstS[(q * 16 + r) * DD + j] = acc[r];
}

__global__ __launch_bounds__(512, 1) void gat_kernel(
    const int* __restrict__ x,
    const float* __restrict__ attr_emb, const float* __restrict__ opt_emb,
    const float* __restrict__ prior,
    const float* __restrict__ Wl, const float* __restrict__ bl,
    const float* __restrict__ Wr, const float* __restrict__ br,
    const float* __restrict__ We, const float* __restrict__ att,
    const float* __restrict__ conv_bias, const float* __restrict__ ln_g,
    const float* __restrict__ ln_b,
    const float* __restrict__ W1, const float* __restrict__ b1,
    const float* __restrict__ W2, const float* __restrict__ b2,
    float* __restrict__ out) {
    extern __shared__ float sm[];
    float* h_s     = sm;                       // 8192
    float* t0_s    = h_s + NN * DD;            // 8192
    float* xl_s    = t0_s + NN * DD;           // 8192
    float* xr_s    = xl_s + NN * DD;           // 8192 (reused as aggregate out)
    float* alpha_s = xr_s + NN * DD;           // 4096 = [H][EE]
    float* eea_s   = alpha_s + HH * EE;        // 1024
    float* rel_s   = eea_s + EE;               // 66 (64 + sum slot)
    int*   esrc_s  = (int*)(rel_s + 66);       // 1024
    int*   off_s   = esrc_s + EE;              // 65

    const int b = blockIdx.x;
    const int tid = threadIdx.x;
    const int lane = tid & 31;
    const int w = tid >> 5;                    // 0..15

    // ---- load sorted edge data + offsets ----
    for (int e = tid; e < EE; e += 512) {
        esrc_s[e] = g_srcp[e];
        eea_s[e]  = g_eap[e];
    }
    if (tid <= NN) off_s[tid] = g_off[tid];

    // ---- T0 = (attr_emb + opt_emb[n, x]) * prior ----
    for (int idx = tid; idx < NN * DD; idx += 512) {
        const int n = idx >> 7, d = idx & 127;
        const int xv = x[b * NN + n];
        const float v = (attr_emb[idx] + opt_emb[(n * KK + xv) * DD + d]) * prior[n];
        t0_s[idx] = v;
        h_s[idx] = v;
    }
    __syncthreads();

    for (int l = 0; l < LL; ++l) {
        // ---- xl = h@Wl + bl ; xr = h@Wr + br ----
        gemm512(h_s, Wl + l * DD * DD, bl + l * DD, xl_s, tid);
        gemm512(h_s, Wr + l * DD * DD, br + l * DD, xr_s, tid);
        __syncthreads();

        // ---- alpha: warp per destination node ----
        {
            const int head = lane >> 3;
            const float4 We4  = *(const float4*)(We  + l * DD + lane * 4);
            const float4 att4 = *(const float4*)(att + l * DD + lane * 4);
            for (int n = w; n < NN; n += 16) {
                const float4 xr4 = *(const float4*)(xr_s + n * DD + lane * 4);
                const int e0 = off_s[n], e1 = off_s[n + 1];
                for (int i = e0; i < e1; ++i) {
                    const int s = esrc_s[i];
                    const float eav = eea_s[i];
                    const float4 xl4 = *(const float4*)(xl_s + s * DD + lane * 4);
                    float z0 = xl4.x + xr4.x + eav * We4.x;
                    float z1 = xl4.y + xr4.y + eav * We4.y;
                    float z2 = xl4.z + xr4.z + eav * We4.z;
                    float z3 = xl4.w + xr4.w + eav * We4.w;
                    z0 = z0 > 0.f ? z0 : 0.2f * z0;
                    z1 = z1 > 0.f ? z1 : 0.2f * z1;
                    z2 = z2 > 0.f ? z2 : 0.2f * z2;
                    z3 = z3 > 0.f ? z3 : 0.2f * z3;
                    float p = z0 * att4.x + z1 * att4.y + z2 * att4.z + z3 * att4.w;
                    p += __shfl_xor_sync(0xffffffffu, p, 1);
                    p += __shfl_xor_sync(0xffffffffu, p, 2);
                    p += __shfl_xor_sync(0xffffffffu, p, 4);
                    if ((lane & 7) == 0) alpha_s[head * EE + i] = p;
                }
            }
        }
        __syncthreads();

        // ---- softmax per (node, head) over contiguous CSR range ----
        if (tid < NN * HH) {
            const int n = tid >> 2, head = tid & 3;
            float* a = alpha_s + head * EE;
            const int e0 = off_s[n], e1 = off_s[n + 1];
            if (e1 > e0) {
                float m = -INFINITY;
                for (int i = e0; i < e1; ++i) m = fmaxf(m, a[i]);
                float den = 0.f;
                for (int i = e0; i < e1; ++i) {
                    const float ex = expf(a[i] - m);
                    a[i] = ex;
                    den += ex;
                }
                const float inv = 1.f / den;
                for (int i = e0; i < e1; ++i) a[i] *= inv;
            }
        }
        __syncthreads();

        // ---- aggregate: out[n,d] = sum over in-edges of xl[src,d]*a  (into xr_s) ----
        {
            const int d = tid & 127;
            const int q = tid >> 7;
            const float* a = alpha_s + (d >> 5) * EE;
            for (int n = q; n < NN; n += 4) {
                float acc = 0.f;
                const int e0 = off_s[n], e1 = off_s[n + 1];
                for (int i = e0; i < e1; ++i)
                    acc = fmaf(xl_s[esrc_s[i] * DD + d], a[i], acc);
                xr_s[n * DD + d] = acc;
            }
        }
        __syncthreads();

        // ---- g = LN(out + conv_bias); h += elu(g)   (warp per node) ----
        for (int n = w; n < NN; n += 16) {
            const float4 gv = *(const float4*)(xr_s + n * DD + lane * 4);
            float v[4];
            v[0] = gv.x + conv_bias[l * DD + lane * 4 + 0];
            v[1] = gv.y + conv_bias[l * DD + lane * 4 + 1];
            v[2] = gv.z + conv_bias[l * DD + lane * 4 + 2];
            v[3] = gv.w + conv_bias[l * DD + lane * 4 + 3];
            float sum = v[0] + v[1] + v[2] + v[3];
            float sq  = v[0]*v[0] + v[1]*v[1] + v[2]*v[2] + v[3]*v[3];
#pragma unroll
            for (int o = 16; o; o >>= 1) {
                sum += __shfl_xor_sync(0xffffffffu, sum, o);
                sq  += __shfl_xor_sync(0xffffffffu, sq, o);
            }
            const float mu = sum * (1.f / DD);
            const float var = sq * (1.f / DD) - mu * mu;
            const float rstd = rsqrtf(var + 1e-5f);
#pragma unroll
            for (int i = 0; i < 4; ++i) {
                const int d = lane * 4 + i;
                float t = (v[i] - mu) * rstd * ln_g[l * DD + d] + ln_b[l * DD + d];
                t = t > 0.f ? t : expm1f(t);
                h_s[n * DD + d] += t;
            }
        }
        __syncthreads();
    }

    // ---- MLP: q = relu([T0, h] @ W1 + b1) -> xl_s ----
    {
        const int j = tid & 127;
        const int q = tid >> 7;
        float acc[16];
        const float bv = b1[j];
#pragma unroll
        for (int r = 0; r < 16; ++r) acc[r] = bv;
        const float* a0 = t0_s + (q * 16) * DD;
        for (int k = 0; k < DD; k += 4) {
            const float w0 = W1[(k + 0) * DD + j];
            const float w1 = W1[(k + 1) * DD + j];
            const float w2 = W1[(k + 2) * DD + j];
            const float w3 = W1[(k + 3) * DD + j];
#pragma unroll
            for (int r = 0; r < 16; ++r) {
                const float4 hv = *(const float4*)(a0 + r * DD + k);
                acc[r] = fmaf(hv.x, w0, acc[r]);
                acc[r] = fmaf(hv.y, w1, acc[r]);
                acc[r] = fmaf(hv.z, w2, acc[r]);
                acc[r] = fmaf(hv.w, w3, acc[r]);
            }
        }
        const float* a1 = h_s + (q * 16) * DD;
        for (int k = 0; k < DD; k += 4) {
            const float w0 = W1[(DD + k + 0) * DD + j];
            const float w1 = W1[(DD + k + 1) * DD + j];
            const float w2 = W1[(DD + k + 2) * DD + j];
            const float w3 = W1[(DD + k + 3) * DD + j];
#pragma unroll
            for (int r = 0; r < 16; ++r) {
                const float4 hv = *(const float4*)(a1 + r * DD + k);
                acc[r] = fmaf(hv.x, w0, acc[r]);
                acc[r] = fmaf(hv.y, w1, acc[r]);
                acc[r] = fmaf(hv.z, w2, acc[r]);
                acc[r] = fmaf(hv.w, w3, acc[r]);
            }
        }
#pragma unroll
        for (int r = 0; r < 16; ++r)
            xl_s[(q * 16 + r) * DD + j] = fmaxf(acc[r], 0.f);
    }
    __syncthreads();

    // ---- rel[n] = sigmoid(q[n].W2 + b2)   (warp per node) ----
    {
        const long long OR = (long long)NB * DD;
        const float4 w24 = *(const float4*)(W2 + lane * 4);
        for (int n = w; n < NN; n += 16) {
            const float4 qv = *(const float4*)(xl_s + n * DD + lane * 4);
            float p = qv.x * w24.x + qv.y * w24.y + qv.z * w24.z + qv.w * w24.w;
#pragma unroll
            for (int o = 16; o; o >>= 1) p += __shfl_xor_sync(0xffffffffu, p, o);
            if (lane == 0) {
                const float r = 1.f / (1.f + expf(-(p + b2[0])));
                rel_s[n] = r;
                out[OR + (long long)b * NN + n] = r;
            }
        }
    }
    __syncthreads();

    // ---- hat_T output: [T0, h] ----
    {
        const long long OH = (long long)NB * DD + (long long)NB * NN;
        for (int idx = tid; idx < NN * DD; idx += 512) {
            const int n = idx >> 7, d = idx & 127;
            const long long base = OH + ((long long)b * NN + n) * (2 * DD);
            out[base + d] = t0_s[idx];
            out[base + DD + d] = h_s[idx];
        }
    }

    // ---- rel sum (warp 0) ----
    if (w == 0) {
        float v = rel_s[lane] + rel_s[lane + 32];
#pragma unroll
        for (int o = 16; o; o >>= 1) v += __shfl_xor_sync(0xffffffffu, v, o);
        if (lane == 0) rel_s[64] = v;
    }

    // ---- f_scale partials: 4 quarters x 128 d (reuse alpha_s) ----
    {
        const int d = tid & 127;
        const int q = tid >> 7;
        float acc = 0.f;
        for (int n = q; n < NN; n += 4)
            acc = fmaf(h_s[n * DD + d], rel_s[n], acc);
        alpha_s[q * DD + d] = acc;
    }
    __syncthreads();
    if (tid < DD) {
        const float num = alpha_s[tid] + alpha_s[DD + tid] +
                          alpha_s[2 * DD + tid] + alpha_s[3 * DD + tid];
        out[(long long)b * DD + tid] = num / (rel_s[64] + 1e-8f);
    }
}

extern "C" void kernel_launch(void* const* d_in, const int* in_sizes, int n_in,
                              void* d_out, int out_size) {
    const int*   x         = (const int*)d_in[0];
    const int*   ei        = (const int*)d_in[1];
    const float* ea        = (const float*)d_in[2];
    const float* attr_emb  = (const float*)d_in[3];
    const float* opt_emb   = (const float*)d_in[4];
    const float* prior     = (const float*)d_in[5];
    const float* Wl        = (const float*)d_in[6];
    const float* bl        = (const float*)d_in[7];
    const float* Wr        = (const float*)d_in[8];
    const float* br        = (const float*)d_in[9];
    const float* We        = (const float*)d_in[10];
    const float* att       = (const float*)d_in[11];
    const float* conv_bias = (const float*)d_in[12];
    const float* ln_g      = (const float*)d_in[13];
    const float* ln_b      = (const float*)d_in[14];
    const float* W1        = (const float*)d_in[15];
    const float* b1        = (const float*)d_in[16];
    const float* W2        = (const float*)d_in[17];
    const float* b2        = (const float*)d_in[18];
    float* out = (float*)d_out;

    const size_t smem = (4 * NN * DD + HH * EE + EE + 66) * sizeof(float)
                        + (EE + 65) * sizeof(int);
    cudaFuncSetAttribute(gat_kernel, cudaFuncAttributeMaxDynamicSharedMemorySize, (int)smem);

    build_csr_kernel<<<1, 64>>>(ei, ea);
    gat_kernel<<<NB, 512, smem>>>(x, attr_emb, opt_emb, prior,
                                  Wl, bl, Wr, br, We, att, conv_bias,
                                  ln_g, ln_b, W1, b1, W2, b2, out);
}

// round 3
// speedup vs baseline: 2.3167x; 1.1599x over previous
#include <cuda_runtime.h>
#include <cuda_bf16.h>
#include <math.h>

#define NB 1024   // batches
#define NN 64     // nodes
#define DD 128    // feature dim
#define EE 1024   // edges
#define HH 4      // heads
#define CC 32     // per-head dim
#define KK 5
#define LL 2

// Edge data sorted by dst (CSR order), built once per launch
__device__ int   g_off[NN + 1];
__device__ int   g_srcp[EE];
__device__ float g_eap[EE];

__global__ void build_csr_kernel(const int* __restrict__ ei, const float* __restrict__ ea) {
    const int n = threadIdx.x;           // 64 threads
    const int* src = ei;
    const int* dst = ei + EE;
    __shared__ int deg[NN];
    int cnt = 0;
    for (int e = 0; e < EE; ++e) cnt += (dst[e] == n);
    deg[n] = cnt;
    __syncthreads();
    if (n == 0) {
        int s = 0;
        for (int i = 0; i < NN; ++i) { g_off[i] = s; s += deg[i]; }
        g_off[NN] = s;
    }
    __syncthreads();
    int p = g_off[n];
    for (int e = 0; e < EE; ++e) {
        if (dst[e] == n) { g_srcp[p] = src[e]; g_eap[p] = ea[e]; ++p; }
    }
}

// ---- packed fp32x2 helpers (B300 FFMA2) ----
__device__ __forceinline__ void fma2(unsigned long long& acc, unsigned long long a,
                                     unsigned long long w) {
    asm("fma.rn.f32x2 %0, %1, %2, %0;" : "+l"(acc) : "l"(a), "l"(w));
}
__device__ __forceinline__ unsigned long long dup2(float v) {
    unsigned long long r;
    asm("mov.b64 %0, {%1, %1};" : "=l"(r) : "r"(__float_as_uint(v)));
    return r;
}
__device__ __forceinline__ void unpack2(unsigned long long v, float& lo, float& hi) {
    asm("mov.b64 {%0, %1}, %2;" : "=f"(lo), "=f"(hi) : "l"(v));
}

struct Acc44 { unsigned long long v[4][2]; };

// accumulate 4x4 output tile over K=128: A (smem, row-major DD) x W (gmem, row-major DD)
__device__ __forceinline__ void gemm_accum(Acc44& acc, const float* __restrict__ A,
                                           const float* __restrict__ W,
                                           int row0, int col0) {
    for (int k = 0; k < DD; k += 4) {
        float4 a[4];
#pragma unroll
        for (int r = 0; r < 4; ++r) a[r] = *(const float4*)(A + (row0 + r) * DD + k);
#pragma unroll
        for (int kk = 0; kk < 4; ++kk) {
            const ulonglong2 wv = *(const ulonglong2*)(W + (k + kk) * DD + col0);
#pragma unroll
            for (int r = 0; r < 4; ++r) {
                const float av = (kk == 0) ? a[r].x : (kk == 1) ? a[r].y : (kk == 2) ? a[r].z : a[r].w;
                const unsigned long long ad = dup2(av);
                fma2(acc.v[r][0], ad, wv.x);
                fma2(acc.v[r][1], ad, wv.y);
            }
        }
    }
}

__device__ __forceinline__ void acc_init_bias(Acc44& acc, const float* __restrict__ bias, int col0) {
    const ulonglong2 bv = *(const ulonglong2*)(bias + col0);
#pragma unroll
    for (int r = 0; r < 4; ++r) { acc.v[r][0] = bv.x; acc.v[r][1] = bv.y; }
}

__device__ __forceinline__ void acc_store(const Acc44& acc, float* __restrict__ dstS,
                                          int row0, int col0) {
#pragma unroll
    for (int r = 0; r < 4; ++r) {
        ulonglong2 o; o.x = acc.v[r][0]; o.y = acc.v[r][1];
        *(ulonglong2*)(dstS + (row0 + r) * DD + col0) = o;
    }
}

__global__ __launch_bounds__(512, 1) void gat_kernel(
    const int* __restrict__ x,
    const float* __restrict__ attr_emb, const float* __restrict__ opt_emb,
    const float* __restrict__ prior,
    const float* __restrict__ Wl, const float* __restrict__ bl,
    const float* __restrict__ Wr, const float* __restrict__ br,
    const float* __restrict__ We, const float* __restrict__ att,
    const float* __restrict__ conv_bias, const float* __restrict__ ln_g,
    const float* __restrict__ ln_b,
    const float* __restrict__ W1, const float* __restrict__ b1,
    const float* __restrict__ W2, const float* __restrict__ b2,
    float* __restrict__ out) {
    extern __shared__ float sm[];
    float* h_s     = sm;                       // 8192
    float* t0_s    = h_s + NN * DD;            // 8192
    float* xl_s    = t0_s + NN * DD;           // 8192
    float* xr_s    = xl_s + NN * DD;           // 8192 (reused as aggregate out)
    float* alpha_s = xr_s + NN * DD;           // 4096 = [H][EE]
    float* eea_s   = alpha_s + HH * EE;        // 1024
    float* rel_s   = eea_s + EE;               // 66 (64 + sum slot)
    int*   esrc_s  = (int*)(rel_s + 66);       // 1024
    int*   off_s   = esrc_s + EE;              // 65

    const int b = blockIdx.x;
    const int tid = threadIdx.x;
    const int lane = tid & 31;
    const int w = tid >> 5;                    // 0..15

    // GEMM tile coords: warp = 4 rows, lane = 4 cols
    const int g_row0 = w * 4;
    const int g_col0 = lane * 4;

    // ---- load sorted edge data + offsets ----
    for (int e = tid; e < EE; e += 512) {
        esrc_s[e] = g_srcp[e];
        eea_s[e]  = g_eap[e];
    }
    if (tid <= NN) off_s[tid] = g_off[tid];

    // ---- T0 = (attr_emb + opt_emb[n, x]) * prior ----
    for (int idx = tid; idx < NN * DD; idx += 512) {
        const int n = idx >> 7, d = idx & 127;
        const int xv = x[b * NN + n];
        const float v = (attr_emb[idx] + opt_emb[(n * KK + xv) * DD + d]) * prior[n];
        t0_s[idx] = v;
        h_s[idx] = v;
    }
    __syncthreads();

    for (int l = 0; l < LL; ++l) {
        // ---- xl = h@Wl + bl ; xr = h@Wr + br  (packed f32x2 GEMMs) ----
        {
            Acc44 acc;
            acc_init_bias(acc, bl + l * DD, g_col0);
            gemm_accum(acc, h_s, Wl + l * DD * DD, g_row0, g_col0);
            acc_store(acc, xl_s, g_row0, g_col0);

            acc_init_bias(acc, br + l * DD, g_col0);
            gemm_accum(acc, h_s, Wr + l * DD * DD, g_row0, g_col0);
            acc_store(acc, xr_s, g_row0, g_col0);
        }
        __syncthreads();

        // ---- alpha: warp per destination node ----
        {
            const int head = lane >> 3;
            const float4 We4  = *(const float4*)(We  + l * DD + lane * 4);
            const float4 att4 = *(const float4*)(att + l * DD + lane * 4);
            for (int n = w; n < NN; n += 16) {
                const float4 xr4 = *(const float4*)(xr_s + n * DD + lane * 4);
                const int e0 = off_s[n], e1 = off_s[n + 1];
#pragma unroll 2
                for (int i = e0; i < e1; ++i) {
                    const int s = esrc_s[i];
                    const float eav = eea_s[i];
                    const float4 xl4 = *(const float4*)(xl_s + s * DD + lane * 4);
                    float z0 = xl4.x + xr4.x + eav * We4.x;
                    float z1 = xl4.y + xr4.y + eav * We4.y;
                    float z2 = xl4.z + xr4.z + eav * We4.z;
                    float z3 = xl4.w + xr4.w + eav * We4.w;
                    z0 = z0 > 0.f ? z0 : 0.2f * z0;
                    z1 = z1 > 0.f ? z1 : 0.2f * z1;
                    z2 = z2 > 0.f ? z2 : 0.2f * z2;
                    z3 = z3 > 0.f ? z3 : 0.2f * z3;
                    float p = z0 * att4.x + z1 * att4.y + z2 * att4.z + z3 * att4.w;
                    p += __shfl_xor_sync(0xffffffffu, p, 1);
                    p += __shfl_xor_sync(0xffffffffu, p, 2);
                    p += __shfl_xor_sync(0xffffffffu, p, 4);
                    if ((lane & 7) == 0) alpha_s[head * EE + i] = p;
                }
            }
        }
        __syncthreads();

        // ---- softmax per node: warp-parallel, lanes = (8 edges) x (4 heads) ----
        {
            const int head = lane >> 3;
            const int el   = lane & 7;
            float* a = alpha_s + head * EE;
            for (int n = w; n < NN; n += 16) {
                const int e0 = off_s[n], e1 = off_s[n + 1];
                float m = -INFINITY;
                for (int i = e0 + el; i < e1; i += 8) m = fmaxf(m, a[i]);
                m = fmaxf(m, __shfl_xor_sync(0xffffffffu, m, 1));
                m = fmaxf(m, __shfl_xor_sync(0xffffffffu, m, 2));
                m = fmaxf(m, __shfl_xor_sync(0xffffffffu, m, 4));
                float s = 0.f;
                for (int i = e0 + el; i < e1; i += 8) {
                    const float ex = __expf(a[i] - m);
                    a[i] = ex;
                    s += ex;
                }
                s += __shfl_xor_sync(0xffffffffu, s, 1);
                s += __shfl_xor_sync(0xffffffffu, s, 2);
                s += __shfl_xor_sync(0xffffffffu, s, 4);
                const float inv = 1.f / s;
                for (int i = e0 + el; i < e1; i += 8) a[i] *= inv;
            }
        }
        __syncthreads();

        // ---- aggregate (f32x2): out[n,d] = sum_in xl[src,d]*a  (into xr_s) ----
        {
            const int dp = tid & 63;          // d-pair index -> d = dp*2
            const int q = tid >> 6;           // 0..7
            const float* a = alpha_s + (dp >> 4) * EE;
            for (int n = q; n < NN; n += 8) {
                unsigned long long acc = 0ull; // (0.f, 0.f)
                const int e0 = off_s[n], e1 = off_s[n + 1];
#pragma unroll 4
                for (int i = e0; i < e1; ++i) {
                    const unsigned long long xv =
                        *(const unsigned long long*)(xl_s + esrc_s[i] * DD + dp * 2);
                    fma2(acc, xv, dup2(a[i]));
                }
                *(unsigned long long*)(xr_s + n * DD + dp * 2) = acc;
            }
        }
        __syncthreads();

        // ---- g = LN(out + conv_bias); h += elu(g)   (warp per node) ----
        for (int n = w; n < NN; n += 16) {
            const float4 gv = *(const float4*)(xr_s + n * DD + lane * 4);
            float v[4];
            v[0] = gv.x + conv_bias[l * DD + lane * 4 + 0];
            v[1] = gv.y + conv_bias[l * DD + lane * 4 + 1];
            v[2] = gv.z + conv_bias[l * DD + lane * 4 + 2];
            v[3] = gv.w + conv_bias[l * DD + lane * 4 + 3];
            float sum = v[0] + v[1] + v[2] + v[3];
            float sq  = v[0]*v[0] + v[1]*v[1] + v[2]*v[2] + v[3]*v[3];
#pragma unroll
            for (int o = 16; o; o >>= 1) {
                sum += __shfl_xor_sync(0xffffffffu, sum, o);
                sq  += __shfl_xor_sync(0xffffffffu, sq, o);
            }
            const float mu = sum * (1.f / DD);
            const float var = sq * (1.f / DD) - mu * mu;
            const float rstd = rsqrtf(var + 1e-5f);
#pragma unroll
            for (int i = 0; i < 4; ++i) {
                const int d = lane * 4 + i;
                float t = (v[i] - mu) * rstd * ln_g[l * DD + d] + ln_b[l * DD + d];
                t = t > 0.f ? t : expm1f(t);
                h_s[n * DD + d] += t;
            }
        }
        __syncthreads();
    }

    // ---- MLP: q = relu([T0, h] @ W1 + b1) -> xl_s  (K=256, two passes) ----
    {
        Acc44 acc;
        acc_init_bias(acc, b1, g_col0);
        gemm_accum(acc, t0_s, W1, g_row0, g_col0);
        gemm_accum(acc, h_s, W1 + DD * DD, g_row0, g_col0);
#pragma unroll
        for (int r = 0; r < 4; ++r) {
            float v0, v1, v2, v3;
            unpack2(acc.v[r][0], v0, v1);
            unpack2(acc.v[r][1], v2, v3);
            float* d = xl_s + (g_row0 + r) * DD + g_col0;
            d[0] = fmaxf(v0, 0.f);
            d[1] = fmaxf(v1, 0.f);
            d[2] = fmaxf(v2, 0.f);
            d[3] = fmaxf(v3, 0.f);
        }
    }
    __syncthreads();

    // ---- rel[n] = sigmoid(q[n].W2 + b2)   (warp per node) ----
    {
        const long long OR = (long long)NB * DD;
        const float4 w24 = *(const float4*)(W2 + lane * 4);
        for (int n = w; n < NN; n += 16) {
            const float4 qv = *(const float4*)(xl_s + n * DD + lane * 4);
            float p = qv.x * w24.x + qv.y * w24.y + qv.z * w24.z + qv.w * w24.w;
#pragma unroll
            for (int o = 16; o; o >>= 1) p += __shfl_xor_sync(0xffffffffu, p, o);
            if (lane == 0) {
                const float r = 1.f / (1.f + expf(-(p + b2[0])));
                rel_s[n] = r;
                out[OR + (long long)b * NN + n] = r;
            }
        }
    }
    __syncthreads();

    // ---- hat_T output: [T0, h] ----
    {
        const long long OH = (long long)NB * DD + (long long)NB * NN;
        for (int idx = tid; idx < NN * DD; idx += 512) {
            const int n = idx >> 7, d = idx & 127;
            const long long base = OH + ((long long)b * NN + n) * (2 * DD);
            out[base + d] = t0_s[idx];
            out[base + DD + d] = h_s[idx];
        }
    }

    // ---- rel sum (warp 0) ----
    if (w == 0) {
        float v = rel_s[lane] + rel_s[lane + 32];
#pragma unroll
        for (int o = 16; o; o >>= 1) v += __shfl_xor_sync(0xffffffffu, v, o);
        if (lane == 0) rel_s[64] = v;
    }

    // ---- f_scale partials: 4 quarters x 128 d (reuse alpha_s) ----
    {
        const int d = tid & 127;
        const int q = tid >> 7;
        float acc = 0.f;
        for (int n = q; n < NN; n += 4)
            acc = fmaf(h_s[n * DD + d], rel_s[n], acc);
        alpha_s[q * DD + d] = acc;
    }
    __syncthreads();
    if (tid < DD) {
        const float num = alpha_s[tid] + alpha_s[DD + tid] +
                          alpha_s[2 * DD + tid] + alpha_s[3 * DD + tid];
        out[(long long)b * DD + tid] = num / (rel_s[64] + 1e-8f);
    }
}

extern "C" void kernel_launch(void* const* d_in, const int* in_sizes, int n_in,
                              void* d_out, int out_size) {
    const int*   x         = (const int*)d_in[0];
    const int*   ei        = (const int*)d_in[1];
    const float* ea        = (const float*)d_in[2];
    const float* attr_emb  = (const float*)d_in[3];
    const float* opt_emb   = (const float*)d_in[4];
    const float* prior     = (const float*)d_in[5];
    const float* Wl        = (const float*)d_in[6];
    const float* bl        = (const float*)d_in[7];
    const float* Wr        = (const float*)d_in[8];
    const float* br        = (const float*)d_in[9];
    const float* We        = (const float*)d_in[10];
    const float* att       = (const float*)d_in[11];
    const float* conv_bias = (const float*)d_in[12];
    const float* ln_g      = (const float*)d_in[13];
    const float* ln_b      = (const float*)d_in[14];
    const float* W1        = (const float*)d_in[15];
    const float* b1        = (const float*)d_in[16];
    const float* W2        = (const float*)d_in[17];
    const float* b2        = (const float*)d_in[18];
    float* out = (float*)d_out;

    const size_t smem = (4 * NN * DD + HH * EE + EE + 66) * sizeof(float)
                        + (EE + 65) * sizeof(int);
    cudaFuncSetAttribute(gat_kernel, cudaFuncAttributeMaxDynamicSharedMemorySize, (int)smem);

    build_csr_kernel<<<1, 64>>>(ei, ea);
    gat_kernel<<<NB, 512, smem>>>(x, attr_emb, opt_emb, prior,
                                  Wl, bl, Wr, br, We, att, conv_bias,
                                  ln_g, ln_b, W1, b1, W2, b2, out);
}

// round 4
// speedup vs baseline: 2.6652x; 1.1505x over previous
#include <cuda_runtime.h>
#include <cuda_bf16.h>
#include <math.h>

#define NB 1024   // batches
#define NN 64     // nodes
#define DD 128    // feature dim
#define EE 1024   // edges
#define HH 4      // heads
#define KK 5
#define LL 2

// Edge data sorted by dst (CSR order), built once per launch
__device__ int   g_off[NN + 1];
__device__ int   g_srcp[EE];
__device__ float g_eap[EE];

__global__ void build_csr_kernel(const int* __restrict__ ei, const float* __restrict__ ea) {
    const int n = threadIdx.x;           // 64 threads
    const int* src = ei;
    const int* dst = ei + EE;
    __shared__ int deg[NN];
    int cnt = 0;
    for (int e = 0; e < EE; ++e) cnt += (dst[e] == n);
    deg[n] = cnt;
    __syncthreads();
    if (n == 0) {
        int s = 0;
        for (int i = 0; i < NN; ++i) { g_off[i] = s; s += deg[i]; }
        g_off[NN] = s;
    }
    __syncthreads();
    int p = g_off[n];
    for (int e = 0; e < EE; ++e) {
        if (dst[e] == n) { g_srcp[p] = src[e]; g_eap[p] = ea[e]; ++p; }
    }
}

// ---- packed fp32x2 helpers (B300 FFMA2) ----
__device__ __forceinline__ void fma2(unsigned long long& acc, unsigned long long a,
                                     unsigned long long w) {
    asm("fma.rn.f32x2 %0, %1, %2, %0;" : "+l"(acc) : "l"(a), "l"(w));
}
__device__ __forceinline__ unsigned long long dup2(float v) {
    unsigned long long r;
    asm("mov.b64 %0, {%1, %1};" : "=l"(r) : "r"(__float_as_uint(v)));
    return r;
}
__device__ __forceinline__ void unpack2(unsigned long long v, float& lo, float& hi) {
    asm("mov.b64 {%0, %1}, %2;" : "=f"(lo), "=f"(hi) : "l"(v));
}

// ---- cp.async helpers ----
__device__ __forceinline__ void cp_async16(unsigned int s, const void* g) {
    asm volatile("cp.async.ca.shared.global [%0], [%1], 16;" :: "r"(s), "l"(g));
}
#define CP_COMMIT() asm volatile("cp.async.commit_group;")
#define CP_WAIT1()  asm volatile("cp.async.wait_group 1;")
#define CP_WAIT0()  asm volatile("cp.async.wait_group 0;")

struct Acc84 { unsigned long long v[8][2]; };

__device__ __forceinline__ void acc_init_bias(Acc84& acc, const float* __restrict__ bias,
                                              int col0) {
    const ulonglong2 bv = *(const ulonglong2*)(bias + col0);
#pragma unroll
    for (int r = 0; r < 8; ++r) { acc.v[r][0] = bv.x; acc.v[r][1] = bv.y; }
}

// acc += A[row0..row0+8][:] @ W[:,col0..col0+4], K=128, W staged through smem panels
// panel: 2 x 2048 floats (2 x 8KB) in the union region
__device__ __forceinline__ void gemm_accum(Acc84& acc, const float* __restrict__ A,
                                           const float* __restrict__ Wg,
                                           float* __restrict__ panel,
                                           int row0, int col0, int tid) {
    const unsigned int p0 = (unsigned int)__cvta_generic_to_shared(panel);
    const char* wsrc = (const char*)Wg;
    cp_async16(p0 + tid * 32,      wsrc + tid * 32);
    cp_async16(p0 + tid * 32 + 16, wsrc + tid * 32 + 16);
    CP_COMMIT();
#pragma unroll 1
    for (int c = 0; c < 8; ++c) {
        if (c < 7) {
            const unsigned int pb = p0 + ((c + 1) & 1) * 8192;
            const char* g = wsrc + (c + 1) * 8192;
            cp_async16(pb + tid * 32,      g + tid * 32);
            cp_async16(pb + tid * 32 + 16, g + tid * 32 + 16);
            CP_COMMIT();
            CP_WAIT1();
        } else {
            CP_WAIT0();
        }
        __syncthreads();
        const float* P = panel + (c & 1) * 2048;
#pragma unroll
        for (int k4 = 0; k4 < 4; ++k4) {
            const int kb = c * 16 + k4 * 4;
            float4 a[8];
#pragma unroll
            for (int r = 0; r < 8; ++r) a[r] = *(const float4*)(A + (row0 + r) * DD + kb);
#pragma unroll
            for (int kk = 0; kk < 4; ++kk) {
                const ulonglong2 wv = *(const ulonglong2*)(P + (k4 * 4 + kk) * DD + col0);
#pragma unroll
                for (int r = 0; r < 8; ++r) {
                    const float av = (kk == 0) ? a[r].x : (kk == 1) ? a[r].y
                                   : (kk == 2) ? a[r].z : a[r].w;
                    const unsigned long long ad = dup2(av);
                    fma2(acc.v[r][0], ad, wv.x);
                    fma2(acc.v[r][1], ad, wv.y);
                }
            }
        }
        __syncthreads();
    }
}

__device__ __forceinline__ void acc_store(const Acc84& acc, float* __restrict__ dstS,
                                          int row0, int col0) {
#pragma unroll
    for (int r = 0; r < 8; ++r) {
        ulonglong2 o; o.x = acc.v[r][0]; o.y = acc.v[r][1];
        *(ulonglong2*)(dstS + (row0 + r) * DD + col0) = o;
    }
}

__global__ __launch_bounds__(256, 2) void gat_kernel(
    const int* __restrict__ x,
    const float* __restrict__ attr_emb, const float* __restrict__ opt_emb,
    const float* __restrict__ prior,
    const float* __restrict__ Wl, const float* __restrict__ bl,
    const float* __restrict__ Wr, const float* __restrict__ br,
    const float* __restrict__ We, const float* __restrict__ att,
    const float* __restrict__ conv_bias, const float* __restrict__ ln_g,
    const float* __restrict__ ln_b,
    const float* __restrict__ W1, const float* __restrict__ b1,
    const float* __restrict__ W2, const float* __restrict__ b2,
    float* __restrict__ out) {
    extern __shared__ float sm[];
    float* h_s   = sm;                     // 8192 floats (h; starts as T0)
    float* xl_s  = h_s + NN * DD;          // 8192
    float* xr_s  = xl_s + NN * DD;         // 8192 (aggregate out; later T0 recomputed)
    float* un_s  = xr_s + NN * DD;         // 4096: union{ W panels | alpha[H][EE] | epilogue }
    unsigned char* esrc_s = (unsigned char*)(un_s + HH * EE);  // 1024 B
    // total = 3*32768 + 16384 + 1024 = 115712 B  (= (228KB - 2KB reserved)/2)

    const int b = blockIdx.x;
    const int tid = threadIdx.x;
    const int lane = tid & 31;
    const int w = tid >> 5;                // 0..7

    const int g_row0 = w * 8;
    const int g_col0 = lane * 4;

    // ---- load packed src indices ----
    for (int e = tid; e < EE; e += 256) esrc_s[e] = (unsigned char)g_srcp[e];

    // ---- h = T0 = (attr_emb + opt_emb[n, x]) * prior ----
    for (int idx = tid; idx < NN * DD; idx += 256) {
        const int n = idx >> 7, d = idx & 127;
        const int xv = x[b * NN + n];
        h_s[idx] = (attr_emb[idx] + opt_emb[(n * KK + xv) * DD + d]) * prior[n];
    }
    __syncthreads();

    for (int l = 0; l < LL; ++l) {
        // ---- xl = h@Wl + bl ; xr = h@Wr + br ----
        {
            Acc84 acc;
            acc_init_bias(acc, bl + l * DD, g_col0);
            gemm_accum(acc, h_s, Wl + l * DD * DD, un_s, g_row0, g_col0, tid);
            acc_store(acc, xl_s, g_row0, g_col0);

            acc_init_bias(acc, br + l * DD, g_col0);
            gemm_accum(acc, h_s, Wr + l * DD * DD, un_s, g_row0, g_col0, tid);
            acc_store(acc, xr_s, g_row0, g_col0);
        }
        __syncthreads();

        float* alpha_s = un_s;             // [H][EE]

        // ---- alpha: warp per destination node ----
        {
            const int head = lane >> 3;
            const float4 We4  = *(const float4*)(We  + l * DD + lane * 4);
            const float4 att4 = *(const float4*)(att + l * DD + lane * 4);
            for (int n = w; n < NN; n += 8) {
                const float4 xr4 = *(const float4*)(xr_s + n * DD + lane * 4);
                const int e0 = g_off[n], e1 = g_off[n + 1];
#pragma unroll 2
                for (int i = e0; i < e1; ++i) {
                    const int s = esrc_s[i];
                    const float eav = g_eap[i];
                    const float4 xl4 = *(const float4*)(xl_s + s * DD + lane * 4);
                    float z0 = xl4.x + xr4.x + eav * We4.x;
                    float z1 = xl4.y + xr4.y + eav * We4.y;
                    float z2 = xl4.z + xr4.z + eav * We4.z;
                    float z3 = xl4.w + xr4.w + eav * We4.w;
                    z0 = z0 > 0.f ? z0 : 0.2f * z0;
                    z1 = z1 > 0.f ? z1 : 0.2f * z1;
                    z2 = z2 > 0.f ? z2 : 0.2f * z2;
                    z3 = z3 > 0.f ? z3 : 0.2f * z3;
                    float p = z0 * att4.x + z1 * att4.y + z2 * att4.z + z3 * att4.w;
                    p += __shfl_xor_sync(0xffffffffu, p, 1);
                    p += __shfl_xor_sync(0xffffffffu, p, 2);
                    p += __shfl_xor_sync(0xffffffffu, p, 4);
                    if ((lane & 7) == 0) alpha_s[head * EE + i] = p;
                }
            }
        }
        __syncthreads();

        // ---- softmax per node: warp-parallel, lanes = (8 edges) x (4 heads) ----
        {
            const int head = lane >> 3;
            const int el   = lane & 7;
            float* a = alpha_s + head * EE;
            for (int n = w; n < NN; n += 8) {
                const int e0 = g_off[n], e1 = g_off[n + 1];
                float m = -INFINITY;
                for (int i = e0 + el; i < e1; i += 8) m = fmaxf(m, a[i]);
                m = fmaxf(m, __shfl_xor_sync(0xffffffffu, m, 1));
                m = fmaxf(m, __shfl_xor_sync(0xffffffffu, m, 2));
                m = fmaxf(m, __shfl_xor_sync(0xffffffffu, m, 4));
                float s = 0.f;
                for (int i = e0 + el; i < e1; i += 8) {
                    const float ex = __expf(a[i] - m);
                    a[i] = ex;
                    s += ex;
                }
                s += __shfl_xor_sync(0xffffffffu, s, 1);
                s += __shfl_xor_sync(0xffffffffu, s, 2);
                s += __shfl_xor_sync(0xffffffffu, s, 4);
                const float inv = 1.f / s;
                for (int i = e0 + el; i < e1; i += 8) a[i] *= inv;
            }
        }
        __syncthreads();

        // ---- aggregate (f32x2): out[n,d] = sum_in xl[src,d]*a  (into xr_s) ----
        {
            const int dp = tid & 63;       // d-pair -> d = dp*2
            const int q = tid >> 6;        // 0..3
            const float* a = alpha_s + (dp >> 4) * EE;
            for (int n = q; n < NN; n += 4) {
                unsigned long long acc = 0ull;
                const int e0 = g_off[n], e1 = g_off[n + 1];
#pragma unroll 4
                for (int i = e0; i < e1; ++i) {
                    const unsigned long long xv =
                        *(const unsigned long long*)(xl_s + (int)esrc_s[i] * DD + dp * 2);
                    fma2(acc, xv, dup2(a[i]));
                }
                *(unsigned long long*)(xr_s + n * DD + dp * 2) = acc;
            }
        }
        __syncthreads();

        // ---- g = LN(out + conv_bias); h += elu(g)   (warp per node) ----
        for (int n = w; n < NN; n += 8) {
            const float4 gv = *(const float4*)(xr_s + n * DD + lane * 4);
            float v[4];
            v[0] = gv.x + conv_bias[l * DD + lane * 4 + 0];
            v[1] = gv.y + conv_bias[l * DD + lane * 4 + 1];
            v[2] = gv.z + conv_bias[l * DD + lane * 4 + 2];
            v[3] = gv.w + conv_bias[l * DD + lane * 4 + 3];
            float sum = v[0] + v[1] + v[2] + v[3];
            float sq  = v[0]*v[0] + v[1]*v[1] + v[2]*v[2] + v[3]*v[3];
#pragma unroll
            for (int o = 16; o; o >>= 1) {
                sum += __shfl_xor_sync(0xffffffffu, sum, o);
                sq  += __shfl_xor_sync(0xffffffffu, sq, o);
            }
            const float mu = sum * (1.f / DD);
            const float var = sq * (1.f / DD) - mu * mu;
            const float rstd = rsqrtf(var + 1e-5f);
#pragma unroll
            for (int i = 0; i < 4; ++i) {
                const int d = lane * 4 + i;
                float t = (v[i] - mu) * rstd * ln_g[l * DD + d] + ln_b[l * DD + d];
                t = t > 0.f ? t : expm1f(t);
                h_s[n * DD + d] += t;
            }
        }
        __syncthreads();
    }

    // ---- recompute T0 into xr_s (free after last layer) ----
    for (int idx = tid; idx < NN * DD; idx += 256) {
        const int n = idx >> 7, d = idx & 127;
        const int xv = x[b * NN + n];
        xr_s[idx] = (attr_emb[idx] + opt_emb[(n * KK + xv) * DD + d]) * prior[n];
    }
    __syncthreads();

    // ---- MLP: q = relu([T0, h] @ W1 + b1) -> xl_s  (K=256, two K=128 passes) ----
    {
        Acc84 acc;
        acc_init_bias(acc, b1, g_col0);
        gemm_accum(acc, xr_s, W1, un_s, g_row0, g_col0, tid);
        gemm_accum(acc, h_s, W1 + DD * DD, un_s, g_row0, g_col0, tid);
#pragma unroll
        for (int r = 0; r < 8; ++r) {
            float v0, v1, v2, v3;
            unpack2(acc.v[r][0], v0, v1);
            unpack2(acc.v[r][1], v2, v3);
            float* d = xl_s + (g_row0 + r) * DD + g_col0;
            d[0] = fmaxf(v0, 0.f);
            d[1] = fmaxf(v1, 0.f);
            d[2] = fmaxf(v2, 0.f);
            d[3] = fmaxf(v3, 0.f);
        }
    }
    __syncthreads();

    float* rel_s = un_s;          // [0..63], relsum at [64], partials at [128..384)

    // ---- rel[n] = sigmoid(q[n].W2 + b2)   (warp per node) ----
    {
        const long long OR = (long long)NB * DD;
        const float4 w24 = *(const float4*)(W2 + lane * 4);
        for (int n = w; n < NN; n += 8) {
            const float4 qv = *(const float4*)(xl_s + n * DD + lane * 4);
            float p = qv.x * w24.x + qv.y * w24.y + qv.z * w24.z + qv.w * w24.w;
#pragma unroll
            for (int o = 16; o; o >>= 1) p += __shfl_xor_sync(0xffffffffu, p, o);
            if (lane == 0) {
                const float r = 1.f / (1.f + expf(-(p + b2[0])));
                rel_s[n] = r;
                out[OR + (long long)b * NN + n] = r;
            }
        }
    }
    __syncthreads();

    // ---- rel sum (warp 0) ----
    if (w == 0) {
        float v = rel_s[lane] + rel_s[lane + 32];
#pragma unroll
        for (int o = 16; o; o >>= 1) v += __shfl_xor_sync(0xffffffffu, v, o);
        if (lane == 0) rel_s[64] = v;
    }

    // ---- f_scale partials ----
    {
        const int d = tid & 127;
        const int q = tid >> 7;            // 0..1
        float acc = 0.f;
        for (int n = q; n < NN; n += 2)
            acc = fmaf(h_s[n * DD + d], rel_s[n], acc);
        un_s[128 + q * DD + d] = acc;
    }

    // ---- hat_T output: [T0(=xr_s), h] ----
    {
        const long long OH = (long long)NB * DD + (long long)NB * NN;
        for (int idx = tid; idx < NN * DD; idx += 256) {
            const int n = idx >> 7, d = idx & 127;
            const long long base = OH + ((long long)b * NN + n) * (2 * DD);
            out[base + d] = xr_s[idx];
            out[base + DD + d] = h_s[idx];
        }
    }
    __syncthreads();

    if (tid < DD) {
        const float num = un_s[128 + tid] + un_s[256 + tid];
        out[(long long)b * DD + tid] = num / (rel_s[64] + 1e-8f);
    }
}

extern "C" void kernel_launch(void* const* d_in, const int* in_sizes, int n_in,
                              void* d_out, int out_size) {
    const int*   x         = (const int*)d_in[0];
    const int*   ei        = (const int*)d_in[1];
    const float* ea        = (const float*)d_in[2];
    const float* attr_emb  = (const float*)d_in[3];
    const float* opt_emb   = (const float*)d_in[4];
    const float* prior     = (const float*)d_in[5];
    const float* Wl        = (const float*)d_in[6];
    const float* bl        = (const float*)d_in[7];
    const float* Wr        = (const float*)d_in[8];
    const float* br        = (const float*)d_in[9];
    const float* We        = (const float*)d_in[10];
    const float* att       = (const float*)d_in[11];
    const float* conv_bias = (const float*)d_in[12];
    const float* ln_g      = (const float*)d_in[13];
    const float* ln_b      = (const float*)d_in[14];
    const float* W1        = (const float*)d_in[15];
    const float* b1        = (const float*)d_in[16];
    const float* W2        = (const float*)d_in[17];
    const float* b2        = (const float*)d_in[18];
    float* out = (float*)d_out;

    const size_t smem = 3 * NN * DD * sizeof(float) + HH * EE * sizeof(float) + EE;
    cudaFuncSetAttribute(gat_kernel, cudaFuncAttributeMaxDynamicSharedMemorySize, (int)smem);

    build_csr_kernel<<<1, 64>>>(ei, ea);
    gat_kernel<<<NB, 256, smem>>>(x, attr_emb, opt_emb, prior,
                                  Wl, bl, Wr, br, We, att, conv_bias,
                                  ln_g, ln_b, W1, b1, W2, b2, out);
}